// round 2
// baseline (speedup 1.0000x reference)
#include <cuda_runtime.h>
#include <cstdint>
#include <cstddef>

// ---------------- problem constants ----------------
#define B_   16
#define P_   512
#define MS_  13          // mlp streams (L+1)
#define D_   768
#define LH_  144         // L*H
#define K_   9216        // LH*DH
#define BP_  8192        // B*P

// ---------------- GEMM tiling ----------------
#define BM   128
#define BN   128
#define BK   32
#define NKT  (K_ / BK)         // 288 k-tiles
#define STAGES 3
#define SA   36                // A smem row stride (words) -> conflict-free frag loads
#define SB   136               // B smem row stride (words) -> conflict-free frag loads
#define AWORDS (BM * SA)       // 4608
#define BWORDS (BK * SB)       // 4352
#define STWORDS (AWORDS + BWORDS)      // 8960
#define MASK_OFF (STAGES * STWORDS)    // 26880
#define SMEM_WORDS (MASK_OFF + LH_)
#define SMEM_BYTES (SMEM_WORDS * 4)    // 108096

__device__ float g_cbase[B_ * D_];

#define DEVI __device__ __forceinline__

DEVI uint32_t smem_u32(const void* p) {
    uint32_t a;
    asm("{ .reg .u64 t; cvta.to.shared.u64 t, %1; cvt.u32.u64 %0, t; }"
        : "=r"(a) : "l"(p));
    return a;
}

DEVI void cp16(uint32_t dst, const void* src) {
    asm volatile("cp.async.cg.shared.global [%0], [%1], 16;" :: "r"(dst), "l"(src));
}
DEVI void cp_commit() { asm volatile("cp.async.commit_group;" ::: "memory"); }
DEVI void cp_wait1() { asm volatile("cp.async.wait_group 1;" ::: "memory"); }
DEVI void cp_wait0() { asm volatile("cp.async.wait_group 0;" ::: "memory"); }

DEVI uint32_t f2tf(float v) {           // round-to-nearest tf32 (avoid truncation bias)
    uint32_t r;
    asm("cvt.rna.tf32.f32 %0, %1;" : "=r"(r) : "f"(v));
    return r;
}

DEVI void mma_tf32(float* d, const uint32_t* a, const uint32_t* b) {
    asm volatile(
        "mma.sync.aligned.m16n8k8.row.col.f32.tf32.tf32.f32 "
        "{%0,%1,%2,%3}, {%4,%5,%6,%7}, {%8,%9}, {%0,%1,%2,%3};"
        : "+f"(d[0]), "+f"(d[1]), "+f"(d[2]), "+f"(d[3])
        : "r"(a[0]), "r"(a[1]), "r"(a[2]), "r"(a[3]), "r"(b[0]), "r"(b[1]));
}

// ---------------- prep: per-(b,d) constant term ----------------
__global__ void cbase_kernel(const float* __restrict__ mlp_mask,
                             const float* __restrict__ attn_mask,
                             const float* __restrict__ mlp_const,
                             const float* __restrict__ attn_const,
                             const float* __restrict__ post_bias) {
    const int i = blockIdx.x * blockDim.x + threadIdx.x;
    if (i >= B_ * D_) return;
    const int b = i / D_, d = i % D_;
    float acc = post_bias[d];
#pragma unroll
    for (int m = 0; m < MS_; m++)
        acc += (1.0f - mlp_mask[b * MS_ + m]) * mlp_const[m * D_ + d];
    for (int lh = 0; lh < LH_; lh++)
        acc += (1.0f - attn_mask[b * LH_ + lh]) * attn_const[lh * D_ + d];
    g_cbase[i] = acc;
}

// ---------------- mlp term + constants -> out (bandwidth-bound) ----------------
__global__ void __launch_bounds__(256)
mlp_kernel(const float* __restrict__ mlp_cache,
           const float* __restrict__ mlp_mask,
           float* __restrict__ out) {
    const int idx = blockIdx.x * blockDim.x + threadIdx.x;  // over BP*D/4
    if (idx >= BP_ * D_ / 4) return;
    const int e = idx * 4;
    const int bp = e / D_;
    const int d = e % D_;
    const int b = bp >> 9;                 // / P_
    const float* src = mlp_cache + (size_t)bp * MS_ * D_ + d;
    const float* mmk = mlp_mask + b * MS_;
    float4 acc = *(const float4*)(&g_cbase[b * D_ + d]);
#pragma unroll
    for (int m = 0; m < MS_; m++) {
        const float s = __ldg(mmk + m);
        const float4 v = *(const float4*)(src + (size_t)m * D_);
        acc.x += s * v.x; acc.y += s * v.y; acc.z += s * v.z; acc.w += s * v.w;
    }
    *(float4*)(out + e) = acc;
}

// ---------------- GEMM: out += (mask * attn_cache) @ W_O  (tf32 mma.sync) ----
__global__ void __launch_bounds__(256, 1)
gemm_kernel(const float* __restrict__ A,          // attn_cache [BP][K]
            const float* __restrict__ W,          // W_O        [K][D]
            const float* __restrict__ attn_mask,  // [B][LH]
            float* __restrict__ out) {            // [BP][D]
    extern __shared__ float sm[];
    const uint32_t smb = smem_u32(sm);
    const int tid = threadIdx.x;
    const int wid = tid >> 5, lane = tid & 31;
    const int mtile = blockIdx.y, ntile = blockIdx.x;
    const int b = mtile >> 2;                 // P_/BM = 4 m-tiles per batch
    const int row0 = mtile * BM, n0 = ntile * BN;
    const int wm = (wid & 1) * 64;            // warp m offset (2x4 warp grid)
    const int wn = (wid >> 1) * 32;           // warp n offset

    if (tid < LH_) sm[MASK_OFF + tid] = attn_mask[b * LH_ + tid];

    // per-thread cp.async coordinates
    const int a_r = tid >> 3;                 // + i*32 rows, i<4
    const int a_c = (tid & 7) * 4;            // word col in BK
    const int b_r = tid >> 5;                 // + i*8 rows, i<4 (wait: 256/32=8 rows/pass, 32 rows => 4 passes)
    const int b_c = (tid & 31) * 4;           // word col in BN

    const float* Abase = A + (size_t)row0 * K_;
    const float* Wbase = W + n0;

#define LOAD_STAGE(ST, KT)                                                          \
    do {                                                                            \
        const uint32_t sa = smb + (uint32_t)(ST) * (STWORDS * 4);                   \
        const float* ag = Abase + (size_t)(KT) * BK;                                \
        _Pragma("unroll")                                                           \
        for (int i = 0; i < 4; i++) {                                               \
            const int r = a_r + i * 32;                                             \
            cp16(sa + (uint32_t)(r * SA + a_c) * 4, ag + (size_t)r * K_ + a_c);     \
        }                                                                           \
        const float* wg = Wbase + (size_t)(KT) * BK * D_;                           \
        _Pragma("unroll")                                                           \
        for (int i = 0; i < 4; i++) {                                               \
            const int r = b_r + i * 8;                                              \
            cp16(sa + (uint32_t)(AWORDS + r * SB + b_c) * 4,                        \
                 wg + (size_t)r * D_ + b_c);                                        \
        }                                                                           \
        cp_commit();                                                                \
    } while (0)

    LOAD_STAGE(0, 0);
    LOAD_STAGE(1, 1);

    float acc[4][4][4];
#pragma unroll
    for (int i = 0; i < 4; i++)
#pragma unroll
        for (int j = 0; j < 4; j++)
#pragma unroll
            for (int k = 0; k < 4; k++) acc[i][j][k] = 0.0f;

    for (int kt = 0; kt < NKT; ++kt) {
        if (kt + 1 < NKT) cp_wait1(); else cp_wait0();
        __syncthreads();
        if (kt + 2 < NKT) LOAD_STAGE((kt + 2) % STAGES, kt + 2);

        const float s = sm[MASK_OFF + (kt >> 1)];   // one (l,h) mask per 64-k block
        const float* As = sm + (kt % STAGES) * STWORDS;
        const float* Bs = As + AWORDS;

#pragma unroll
        for (int ks = 0; ks < 4; ks++) {
            uint32_t af[4][4], bf[4][2];
#pragma unroll
            for (int im = 0; im < 4; im++) {
                const float* ap = As + (wm + im * 16 + (lane >> 2)) * SA
                                     + ks * 8 + (lane & 3);
                af[im][0] = f2tf(ap[0]);
                af[im][1] = f2tf(ap[8 * SA]);
                af[im][2] = f2tf(ap[4]);
                af[im][3] = f2tf(ap[8 * SA + 4]);
            }
#pragma unroll
            for (int in_ = 0; in_ < 4; in_++) {
                const float* bp = Bs + (ks * 8 + (lane & 3)) * SB
                                     + wn + in_ * 8 + (lane >> 2);
                bf[in_][0] = f2tf(bp[0] * s);
                bf[in_][1] = f2tf(bp[4 * SB] * s);
            }
#pragma unroll
            for (int im = 0; im < 4; im++)
#pragma unroll
                for (int in_ = 0; in_ < 4; in_++)
                    mma_tf32(acc[im][in_], af[im], bf[in_]);
        }
    }

    // epilogue: RMW add onto out (mlp kernel already wrote base)
#pragma unroll
    for (int im = 0; im < 4; im++) {
        const int r = row0 + wm + im * 16 + (lane >> 2);
#pragma unroll
        for (int in_ = 0; in_ < 4; in_++) {
            const int c = n0 + wn + in_ * 8 + (lane & 3) * 2;
            float2* p0 = (float2*)(out + (size_t)r * D_ + c);
            float2* p1 = (float2*)(out + (size_t)(r + 8) * D_ + c);
            float2 v0 = *p0, v1 = *p1;
            v0.x += acc[im][in_][0]; v0.y += acc[im][in_][1];
            v1.x += acc[im][in_][2]; v1.y += acc[im][in_][3];
            *p0 = v0; *p1 = v1;
        }
    }
}

// ---------------- launch ----------------
extern "C" void kernel_launch(void* const* d_in, const int* in_sizes, int n_in,
                              void* d_out, int out_size) {
    const float* mlp_cache  = (const float*)d_in[0];
    const float* attn_cache = (const float*)d_in[1];
    const float* mlp_mask   = (const float*)d_in[2];
    const float* attn_mask  = (const float*)d_in[3];
    const float* mlp_const  = (const float*)d_in[4];
    const float* attn_const = (const float*)d_in[5];
    const float* W_O        = (const float*)d_in[6];
    const float* post_bias  = (const float*)d_in[7];
    float* out = (float*)d_out;

    cudaFuncSetAttribute(gemm_kernel, cudaFuncAttributeMaxDynamicSharedMemorySize, SMEM_BYTES);

    cbase_kernel<<<(B_ * D_ + 255) / 256, 256>>>(mlp_mask, attn_mask, mlp_const,
                                                 attn_const, post_bias);
    mlp_kernel<<<(BP_ * D_ / 4 + 255) / 256, 256>>>(mlp_cache, mlp_mask, out);
    gemm_kernel<<<dim3(D_ / BN, BP_ / BM), 256, SMEM_BYTES>>>(attn_cache, W_O,
                                                              attn_mask, out);
}